// round 13
// baseline (speedup 1.0000x reference)
#include <cuda_runtime.h>
#include <cuda_fp16.h>

#define FEAT 1024
#define NH   16
#define HD   64
#define BATCH 8
#define SEQ  1024

// ---------------- scratch (device globals; no allocation) ----------------
__device__ __half g_x16[8192*1024];
__device__ __half g_wq16[3072*1024];
__device__ __half g_wp16[1024*1024];
__device__ __half g_a16[8192*1024];
__device__ __half g_q16[8192*1024];
__device__ __half g_k16[8192*1024];
__device__ __half g_v16[8192*1024];

// ---------------- helpers ----------------
__device__ __forceinline__ void ldsm4(unsigned r[4], unsigned addr) {
    asm volatile("ldmatrix.sync.aligned.m8n8.x4.shared.b16 {%0,%1,%2,%3}, [%4];\n"
                 : "=r"(r[0]), "=r"(r[1]), "=r"(r[2]), "=r"(r[3]) : "r"(addr));
}
__device__ __forceinline__ void mma_f16(float c[4], const unsigned a[4], const unsigned b[2]) {
    asm volatile("mma.sync.aligned.m16n8k16.row.col.f32.f16.f16.f32 "
                 "{%0,%1,%2,%3}, {%4,%5,%6,%7}, {%8,%9}, {%0,%1,%2,%3};\n"
                 : "+f"(c[0]), "+f"(c[1]), "+f"(c[2]), "+f"(c[3])
                 : "r"(a[0]), "r"(a[1]), "r"(a[2]), "r"(a[3]), "r"(b[0]), "r"(b[1]));
}
__device__ __forceinline__ void cp16(unsigned dst, const void* src) {
    asm volatile("cp.async.cg.shared.global [%0], [%1], 16;\n" :: "r"(dst), "l"(src));
}
__device__ __forceinline__ unsigned pack_h2(float lo, float hi) {
    __half2 h = __floats2half2_rn(lo, hi);
    return *(unsigned*)&h;
}

// ---------------- fp32 -> fp16 convert ----------------
__global__ __launch_bounds__(256)
void cvt_fp16(const float* __restrict__ src, __half* __restrict__ dst, int n4)
{
    int i = blockIdx.x * blockDim.x + threadIdx.x;
    if (i >= n4) return;
    float4 v = ((const float4*)src)[i];
    uint2 o;
    o.x = pack_h2(v.x, v.y);
    o.y = pack_h2(v.z, v.w);
    ((uint2*)dst)[i] = o;
}

// ---------------- fp16 tensor-core GEMM: C = A @ W^T + bias ----------------
// 128 threads / 4 warps, warp tile 64x64, K-chunk 32, double-buffered smem.
#define AST 40                   // fp16 elems per smem row (32 + 8 pad)
#define PLANE_B (128*AST*2)      // 10240 bytes per plane
#define BUF_B (2*PLANE_B)        // A, W = 20480
#define GEMM_SMEM (2*BUF_B)      // 40960 double-buffered (2 CTA = 80KB)

// EPILOGUE 0: scatter fp16 to q/k/v ; EPILOGUE 1: fp32 row-major to outf
template<int EPILOGUE>
__global__ __launch_bounds__(128, 2)
void gemm_f16(const __half* __restrict__ A16, const __half* __restrict__ W16,
              const float* __restrict__ bias, float* __restrict__ outf,
              __half* __restrict__ oq, __half* __restrict__ ok, __half* __restrict__ ov,
              int N, int K)
{
    extern __shared__ __half sm[];
    const int tid = threadIdx.x;
    const int bm = blockIdx.y * 128, bn = blockIdx.x * 128;
    const int w = tid >> 5, l = tid & 31;
    const int wm = w >> 1, wn = w & 1;       // 2x2 warp grid; warp tile 64x64

    // staging: 1 thread per row; each stages 4x16B segments per plane
    const __half* gA = A16 + (size_t)(bm + tid) * K;
    const __half* gB = W16 + (size_t)(bn + tid) * K;

    const unsigned sbase = (unsigned)__cvta_generic_to_shared(sm);
    const unsigned sst = sbase + tid * (AST*2);

    float acc[4][8][4];
    #pragma unroll
    for (int i = 0; i < 4; i++)
        #pragma unroll
        for (int j = 0; j < 8; j++)
            #pragma unroll
            for (int r = 0; r < 4; r++) acc[i][j][r] = 0.f;

    auto issue = [&](int k0, int buf) {
        unsigned d = sst + buf * BUF_B;
        #pragma unroll
        for (int i = 0; i < 4; i++) {
            cp16(d + i*16,           gA + k0 + i*8);
            cp16(d + PLANE_B + i*16, gB + k0 + i*8);
        }
        asm volatile("cp.async.commit_group;\n" ::: "memory");
    };

    issue(0, 0);
    int buf = 0;
    for (int k0 = 0; k0 < K; k0 += 32) {
        const bool more = (k0 + 32) < K;
        if (more) {
            issue(k0 + 32, buf ^ 1);
            asm volatile("cp.async.wait_group 1;\n" ::: "memory");
        } else {
            asm volatile("cp.async.wait_group 0;\n" ::: "memory");
        }
        __syncthreads();

        unsigned base = sbase + buf * BUF_B;
        #pragma unroll
        for (int g = 0; g < 2; g++) {
            unsigned ah[4][4], bh[8][2];
            const int acol = g * 16 + (l >> 4) * 8;
            #pragma unroll
            for (int mt = 0; mt < 4; mt++) {
                int row = wm * 64 + mt * 16 + (l & 15);
                ldsm4(ah[mt], base + row * (AST*2) + acol * 2);
            }
            {
                const int quad = l >> 3;
                const int nsub = quad >> 1, khalf = quad & 1;
                #pragma unroll
                for (int p = 0; p < 4; p++) {
                    int row = wn * 64 + (p*2 + nsub) * 8 + (l & 7);
                    int col = g * 16 + khalf * 8;
                    unsigned t[4];
                    ldsm4(t, base + PLANE_B + row * (AST*2) + col * 2);
                    bh[p*2][0] = t[0]; bh[p*2][1] = t[1];
                    bh[p*2+1][0] = t[2]; bh[p*2+1][1] = t[3];
                }
            }
            #pragma unroll
            for (int mt = 0; mt < 4; mt++)
                #pragma unroll
                for (int nt = 0; nt < 8; nt++)
                    mma_f16(acc[mt][nt], ah[mt], bh[nt]);
        }
        __syncthreads();
        buf ^= 1;
    }

    const int gid = l >> 2, qid = l & 3;
    #pragma unroll
    for (int mt = 0; mt < 4; mt++) {
        #pragma unroll
        for (int nt = 0; nt < 8; nt++) {
            int n0 = bn + wn * 64 + nt * 8 + qid * 2;
            float bx = bias[n0], by = bias[n0 + 1];
            #pragma unroll
            for (int half = 0; half < 2; half++) {
                int m = bm + wm * 64 + mt * 16 + gid + half * 8;
                float cx = acc[mt][nt][half*2 + 0] + bx;
                float cy = acc[mt][nt][half*2 + 1] + by;
                if (EPILOGUE == 0) {
                    int b = m >> 10, t = m & 1023;
                    int s = n0 >> 10, r = n0 & 1023;
                    int hh = r >> 6, d = r & 63;
                    size_t off = ((size_t)(b*NH + hh)*SEQ + t) * HD + d;
                    __half* dh = (s == 0 ? oq : (s == 1 ? ok : ov));
                    *(unsigned*)(dh + off) = pack_h2(cx, cy);
                } else {
                    float2 v2 = {cx, cy};
                    *(float2*)(outf + (size_t)m * N + n0) = v2;
                }
            }
        }
    }
}

// ---------------- fp16 tensor-core flash attention ----------------
// CTA: 128 q rows of one (b,h); key tiles of 64. 8 warps, warp = 16 rows.
#define QST 72
#define KST 72
#define VST 72
#define SM_Q 0
#define SM_K (128*QST)
#define SM_V (128*QST + 64*KST)
#define SM_TOT (128*QST + 64*KST + 64*VST)
#define ATTN_SMEM (SM_TOT*2 + 1024)

__global__ __launch_bounds__(256)
void flash_attn_f16(const __half* __restrict__ q16, const __half* __restrict__ k16,
                    const __half* __restrict__ v16,
                    const unsigned char* __restrict__ pad, const float* __restrict__ scale_p,
                    __half* __restrict__ outa)
{
    extern __shared__ __half smh[];
    unsigned char* spad = (unsigned char*)(smh + SM_TOT);
    const unsigned sbase = (unsigned)__cvta_generic_to_shared(smh);

    const int bh = blockIdx.x;
    const int b = bh >> 4, h = bh & 15;
    const int qb = (int)(gridDim.y - 1) - (int)blockIdx.y;   // heavy first
    const int q0 = qb * 128;
    const int tid = threadIdx.x;
    const int wid = tid >> 5, l = tid & 31;
    const int gid = l >> 2, qd = l & 3;
    const float scale = *scale_p;

    const int brow = ((l >> 4) & 1) * 8 + (l & 7);
    const int bcol = ((l >> 3) & 1) * 8;

    ((int*)spad)[tid] = ((const int*)(pad + (size_t)b*SEQ))[tid];

    // Q tile (persistent)
    {
        const __half* qs = q16 + ((size_t)bh*SEQ + q0)*HD;
        #pragma unroll
        for (int it = 0; it < 4; it++) {
            int lin = it*256 + tid;
            int row = lin >> 3, seg = lin & 7;
            cp16(sbase + (SM_Q + row*QST)*2 + seg*16, qs + (size_t)row*HD + seg*8);
        }
        asm volatile("cp.async.commit_group;\ncp.async.wait_group 0;\n" ::: "memory");
    }
    __syncthreads();

    unsigned qf[4][4];
    {
        int row = wid*16 + (l & 15);
        int csel = (l >> 4) * 8;
        #pragma unroll
        for (int ks = 0; ks < 4; ks++)
            ldsm4(qf[ks], sbase + (SM_Q + row*QST + ks*16 + csel)*2);
    }

    float O[8][4];
    #pragma unroll
    for (int nt = 0; nt < 8; nt++)
        #pragma unroll
        for (int r = 0; r < 4; r++) O[nt][r] = 0.f;
    float mrow[2] = {-1e30f, -1e30f};
    float lrow[2] = {0.f, 0.f};

    const int r0g = q0 + wid*16 + gid;
    const int r1g = r0g + 8;
    const int nkt = 2*qb + 2;

    for (int kt = 0; kt < nkt; kt++) {
        const int kb = kt * 64;
        __syncthreads();

        // K tile via cp.async
        {
            const __half* ks_ = k16 + ((size_t)bh*SEQ + kb)*HD;
            #pragma unroll
            for (int it = 0; it < 2; it++) {
                int lin = it*256 + tid;
                int row = lin >> 3, seg = lin & 7;
                cp16(sbase + (SM_K + row*KST)*2 + seg*16, ks_ + (size_t)row*HD + seg*8);
            }
            asm volatile("cp.async.commit_group;\n" ::: "memory");
        }
        // V tile, transposed [d][key]
        {
            int t = tid >> 2;
            int db = (tid & 3) * 16;
            const __half* vs = v16 + ((size_t)bh*SEQ + kb + t)*HD + db;
            #pragma unroll
            for (int j = 0; j < 4; j++) {
                uint2 u = *(const uint2*)(vs + j*4);
                __half2 a = *(__half2*)&u.x;
                __half2 c = *(__half2*)&u.y;
                smh[SM_V + (db + j*4 + 0)*VST + t] = a.x;
                smh[SM_V + (db + j*4 + 1)*VST + t] = a.y;
                smh[SM_V + (db + j*4 + 2)*VST + t] = c.x;
                smh[SM_V + (db + j*4 + 3)*VST + t] = c.y;
            }
        }
        asm volatile("cp.async.wait_group 0;\n" ::: "memory");
        __syncthreads();

        // ---- S = Q K^T ----
        float sacc[8][4];
        #pragma unroll
        for (int nt = 0; nt < 8; nt++)
            #pragma unroll
            for (int r = 0; r < 4; r++) sacc[nt][r] = 0.f;

        #pragma unroll
        for (int ks = 0; ks < 4; ks++) {
            #pragma unroll
            for (int p = 0; p < 4; p++) {
                unsigned k4[4];
                ldsm4(k4, sbase + (SM_K + (p*16 + brow)*KST + ks*16 + bcol)*2);
                unsigned b0[2] = {k4[0], k4[1]}, b1[2] = {k4[2], k4[3]};
                mma_f16(sacc[2*p],   qf[ks], b0);
                mma_f16(sacc[2*p+1], qf[ks], b1);
            }
        }

        // ---- scale + mask + online softmax ----
        float tmax0 = -1e30f, tmax1 = -1e30f;
        const bool do_causal = (kb + 63 > q0 + wid*16);
        #pragma unroll
        for (int nt = 0; nt < 8; nt++) {
            int c0 = kb + nt*8 + qd*2;
            bool pm0 = spad[c0] != 0, pm1 = spad[c0+1] != 0;
            float v00 = sacc[nt][0] * scale;
            float v01 = sacc[nt][1] * scale;
            float v10 = sacc[nt][2] * scale;
            float v11 = sacc[nt][3] * scale;
            if (pm0) { v00 = -1e30f; v10 = -1e30f; }
            if (pm1) { v01 = -1e30f; v11 = -1e30f; }
            if (do_causal) {
                if (c0   > r0g) v00 = -1e30f;
                if (c0+1 > r0g) v01 = -1e30f;
                if (c0   > r1g) v10 = -1e30f;
                if (c0+1 > r1g) v11 = -1e30f;
            }
            sacc[nt][0] = v00; sacc[nt][1] = v01;
            sacc[nt][2] = v10; sacc[nt][3] = v11;
            tmax0 = fmaxf(tmax0, fmaxf(v00, v01));
            tmax1 = fmaxf(tmax1, fmaxf(v10, v11));
        }
        tmax0 = fmaxf(tmax0, __shfl_xor_sync(0xffffffffu, tmax0, 1));
        tmax0 = fmaxf(tmax0, __shfl_xor_sync(0xffffffffu, tmax0, 2));
        tmax1 = fmaxf(tmax1, __shfl_xor_sync(0xffffffffu, tmax1, 1));
        tmax1 = fmaxf(tmax1, __shfl_xor_sync(0xffffffffu, tmax1, 2));

        float mn0 = fmaxf(mrow[0], tmax0);
        float mn1 = fmaxf(mrow[1], tmax1);
        float cf0 = __expf(mrow[0] - mn0);
        float cf1 = __expf(mrow[1] - mn1);
        mrow[0] = mn0; mrow[1] = mn1;

        float rs0 = 0.f, rs1 = 0.f;
        unsigned pf[8][2];
        #pragma unroll
        for (int nt = 0; nt < 8; nt++) {
            float p00 = __expf(sacc[nt][0] - mn0);
            float p01 = __expf(sacc[nt][1] - mn0);
            float p10 = __expf(sacc[nt][2] - mn1);
            float p11 = __expf(sacc[nt][3] - mn1);
            rs0 += p00 + p01;
            rs1 += p10 + p11;
            pf[nt][0] = pack_h2(p00, p01);
            pf[nt][1] = pack_h2(p10, p11);
        }
        rs0 += __shfl_xor_sync(0xffffffffu, rs0, 1);
        rs0 += __shfl_xor_sync(0xffffffffu, rs0, 2);
        rs1 += __shfl_xor_sync(0xffffffffu, rs1, 1);
        rs1 += __shfl_xor_sync(0xffffffffu, rs1, 2);
        lrow[0] = lrow[0] * cf0 + rs0;
        lrow[1] = lrow[1] * cf1 + rs1;
        #pragma unroll
        for (int nt = 0; nt < 8; nt++) {
            O[nt][0] *= cf0; O[nt][1] *= cf0;
            O[nt][2] *= cf1; O[nt][3] *= cf1;
        }

        // ---- O += P V ----
        #pragma unroll
        for (int ks = 0; ks < 4; ks++) {
            unsigned pa[4] = {pf[2*ks][0], pf[2*ks][1], pf[2*ks+1][0], pf[2*ks+1][1]};
            #pragma unroll
            for (int p = 0; p < 4; p++) {
                unsigned v4[4];
                ldsm4(v4, sbase + (SM_V + (p*16 + brow)*VST + ks*16 + bcol)*2);
                unsigned b0[2] = {v4[0], v4[1]}, b1[2] = {v4[2], v4[3]};
                mma_f16(O[2*p],   pa, b0);
                mma_f16(O[2*p+1], pa, b1);
            }
        }
    }

    // ---- epilogue: normalize, store fp16 [b, t, h*64+d] ----
    float inv0 = 1.f / lrow[0];
    float inv1 = 1.f / lrow[1];
    #pragma unroll
    for (int nt = 0; nt < 8; nt++) {
        float o00 = O[nt][0] * inv0, o01 = O[nt][1] * inv0;
        float o10 = O[nt][2] * inv1, o11 = O[nt][3] * inv1;
        int col = h*HD + nt*8 + qd*2;
        *(unsigned*)(outa + (size_t)(b*SEQ + r0g) * FEAT + col) = pack_h2(o00, o01);
        *(unsigned*)(outa + (size_t)(b*SEQ + r1g) * FEAT + col) = pack_h2(o10, o11);
    }
}

// ---------------- launch ----------------
extern "C" void kernel_launch(void* const* d_in, const int* in_sizes, int n_in,
                              void* d_out, int out_size)
{
    const float* x    = (const float*)d_in[0];
    const unsigned char* pad = (const unsigned char*)d_in[1];
    const float* Wqkv = (const float*)d_in[2];
    const float* bqkv = (const float*)d_in[3];
    const float* Wp   = (const float*)d_in[4];
    const float* bp   = (const float*)d_in[5];
    const float* scale = (const float*)d_in[6];
    float* out = (float*)d_out;

    __half *x16, *wq16, *wp16, *a16, *q16, *k16, *v16;
    cudaGetSymbolAddress((void**)&x16, g_x16);
    cudaGetSymbolAddress((void**)&wq16, g_wq16);
    cudaGetSymbolAddress((void**)&wp16, g_wp16);
    cudaGetSymbolAddress((void**)&a16, g_a16);
    cudaGetSymbolAddress((void**)&q16, g_q16);
    cudaGetSymbolAddress((void**)&k16, g_k16);
    cudaGetSymbolAddress((void**)&v16, g_v16);

    cudaFuncSetAttribute(gemm_f16<0>, cudaFuncAttributeMaxDynamicSharedMemorySize, GEMM_SMEM);
    cudaFuncSetAttribute(gemm_f16<1>, cudaFuncAttributeMaxDynamicSharedMemorySize, GEMM_SMEM);
    cudaFuncSetAttribute(flash_attn_f16, cudaFuncAttributeMaxDynamicSharedMemorySize, ATTN_SMEM);

    cvt_fp16<<<(8192*1024/4 + 255)/256, 256>>>(x, x16, 8192*1024/4);
    cvt_fp16<<<(3072*1024/4 + 255)/256, 256>>>(Wqkv, wq16, 3072*1024/4);
    cvt_fp16<<<(1024*1024/4 + 255)/256, 256>>>(Wp, wp16, 1024*1024/4);

    dim3 g1(3072/128, 8192/128);
    gemm_f16<0><<<g1, 128, GEMM_SMEM>>>(x16, wq16, bqkv, nullptr, q16, k16, v16, 3072, 1024);

    dim3 g2(BATCH*NH, SEQ/128);
    flash_attn_f16<<<g2, 256, ATTN_SMEM>>>(q16, k16, v16, pad, scale, a16);

    dim3 g3(1024/128, 8192/128);
    gemm_f16<1><<<g3, 128, GEMM_SMEM>>>(a16, wp16, bp, out, nullptr, nullptr, nullptr, 1024, 1024);
}

// round 14
// speedup vs baseline: 1.2705x; 1.2705x over previous
#include <cuda_runtime.h>
#include <cuda_fp16.h>

#define FEAT 1024
#define NH   16
#define HD   64
#define BATCH 8
#define SEQ  1024

// ---------------- scratch (device globals; no allocation) ----------------
__device__ __half g_x16[8192*1024];
__device__ __half g_wq16[3072*1024];
__device__ __half g_wp16[1024*1024];
__device__ __half g_a16[8192*1024];
__device__ __half g_q16[8192*1024];
__device__ __half g_k16[8192*1024];
__device__ __half g_v16[8192*1024];

// ---------------- helpers ----------------
__device__ __forceinline__ void ldsm4(unsigned r[4], unsigned addr) {
    asm volatile("ldmatrix.sync.aligned.m8n8.x4.shared.b16 {%0,%1,%2,%3}, [%4];\n"
                 : "=r"(r[0]), "=r"(r[1]), "=r"(r[2]), "=r"(r[3]) : "r"(addr));
}
__device__ __forceinline__ void mma_f16(float c[4], const unsigned a[4], const unsigned b[2]) {
    asm volatile("mma.sync.aligned.m16n8k16.row.col.f32.f16.f16.f32 "
                 "{%0,%1,%2,%3}, {%4,%5,%6,%7}, {%8,%9}, {%0,%1,%2,%3};\n"
                 : "+f"(c[0]), "+f"(c[1]), "+f"(c[2]), "+f"(c[3])
                 : "r"(a[0]), "r"(a[1]), "r"(a[2]), "r"(a[3]), "r"(b[0]), "r"(b[1]));
}
__device__ __forceinline__ void cp16(unsigned dst, const void* src) {
    asm volatile("cp.async.cg.shared.global [%0], [%1], 16;\n" :: "r"(dst), "l"(src));
}
__device__ __forceinline__ unsigned pack_h2(float lo, float hi) {
    __half2 h = __floats2half2_rn(lo, hi);
    return *(unsigned*)&h;
}

// ---------------- fp32 -> fp16 convert (all three tensors, one launch) ----------------
#define N4_X  (8192*1024/4)
#define N4_WQ (3072*1024/4)
#define N4_WP (1024*1024/4)
__global__ __launch_bounds__(256)
void cvt3_fp16(const float* __restrict__ x, const float* __restrict__ wq,
               const float* __restrict__ wp,
               __half* __restrict__ x16, __half* __restrict__ wq16,
               __half* __restrict__ wp16)
{
    int i = blockIdx.x * blockDim.x + threadIdx.x;
    const float* s; __half* d; int j;
    if (i < N4_X)                 { s = x;  d = x16;  j = i; }
    else if (i < N4_X + N4_WQ)    { s = wq; d = wq16; j = i - N4_X; }
    else if (i < N4_X + N4_WQ + N4_WP) { s = wp; d = wp16; j = i - N4_X - N4_WQ; }
    else return;
    float4 v = ((const float4*)s)[j];
    uint2 o;
    o.x = pack_h2(v.x, v.y);
    o.y = pack_h2(v.z, v.w);
    ((uint2*)d)[j] = o;
}

// ---------------- fp16 tensor-core GEMM: C = A @ W^T + bias ----------------
// 256 threads / 8 warps, warp tile 64x32, K-chunk 32, double-buffered smem.
// Cross-window fragment holding: g1 fragments of window w are MMA'd after the
// sync of window w+1, overlapping the post-barrier LDSM burst.
#define AST 40                   // fp16 elems per smem row (32 + 8 pad)
#define PLANE_B (128*AST*2)      // 10240 bytes per plane
#define BUF_B (2*PLANE_B)        // A, W = 20480
#define GEMM_SMEM (2*BUF_B)      // 40960 double-buffered

// EPILOGUE 0: scatter fp16 to q/k/v ; EPILOGUE 1: fp32 row-major to outf
template<int EPILOGUE>
__global__ __launch_bounds__(256, 2)
void gemm_f16(const __half* __restrict__ A16, const __half* __restrict__ W16,
              const float* __restrict__ bias, float* __restrict__ outf,
              __half* __restrict__ oq, __half* __restrict__ ok, __half* __restrict__ ov,
              int N, int K)
{
    extern __shared__ __half sm[];
    const int tid = threadIdx.x;
    const int bm = blockIdx.y * 128, bn = blockIdx.x * 128;
    const int w = tid >> 5, l = tid & 31;
    const int wm = w >> 2, wn = w & 3;       // 2x4 warp grid; warp tile 64x32

    // staging: 2 threads per row; each stages 2x16B segments per plane
    const int lrow = tid >> 1;
    const int lcol = (tid & 1) * 16;
    const __half* gA = A16 + (size_t)(bm + lrow) * K + lcol;
    const __half* gB = W16 + (size_t)(bn + lrow) * K + lcol;

    const unsigned sbase = (unsigned)__cvta_generic_to_shared(sm);
    const unsigned sst = sbase + lrow * (AST*2) + lcol * 2;

    float acc[4][4][4];
    #pragma unroll
    for (int i = 0; i < 4; i++)
        #pragma unroll
        for (int j = 0; j < 4; j++)
            #pragma unroll
            for (int r = 0; r < 4; r++) acc[i][j][r] = 0.f;

    auto issue = [&](int k0, int buf) {
        unsigned d = sst + buf * BUF_B;
        cp16(d,             gA + k0); cp16(d + 16,             gA + k0 + 8);
        cp16(d + PLANE_B,   gB + k0); cp16(d + PLANE_B + 16,   gB + k0 + 8);
        asm volatile("cp.async.commit_group;\n" ::: "memory");
    };

    auto ldsm_frags = [&](unsigned base, int g, unsigned ah[4][4], unsigned bh[4][2]) {
        const int acol = g * 16 + (l >> 4) * 8;
        #pragma unroll
        for (int mt = 0; mt < 4; mt++) {
            int row = wm * 64 + mt * 16 + (l & 15);
            ldsm4(ah[mt], base + row * (AST*2) + acol * 2);
        }
        const int quad = l >> 3;
        const int nsub = quad >> 1, khalf = quad & 1;
        #pragma unroll
        for (int p = 0; p < 2; p++) {
            int row = wn * 32 + (p*2 + nsub) * 8 + (l & 7);
            int col = g * 16 + khalf * 8;
            unsigned t[4];
            ldsm4(t, base + PLANE_B + row * (AST*2) + col * 2);
            bh[p*2][0] = t[0]; bh[p*2][1] = t[1];
            bh[p*2+1][0] = t[2]; bh[p*2+1][1] = t[3];
        }
    };

    unsigned ah0[4][4], bh0[4][2];     // g0 fragments (current window)
    unsigned ah1[4][4], bh1[4][2];     // g1 fragments (held across boundary)

    issue(0, 0);
    int buf = 0;
    for (int k0 = 0; k0 < K; k0 += 32) {
        const bool more = (k0 + 32) < K;
        if (more) {
            issue(k0 + 32, buf ^ 1);
            asm volatile("cp.async.wait_group 1;\n" ::: "memory");
        } else {
            asm volatile("cp.async.wait_group 0;\n" ::: "memory");
        }
        __syncthreads();

        unsigned base = sbase + buf * BUF_B;
        // LDSM g0 first; overlap its latency with the previous window's g1 MMAs
        ldsm_frags(base, 0, ah0, bh0);
        if (k0 > 0) {
            #pragma unroll
            for (int mt = 0; mt < 4; mt++)
                #pragma unroll
                for (int nt = 0; nt < 4; nt++)
                    mma_f16(acc[mt][nt], ah1[mt], bh1[nt]);
        }
        ldsm_frags(base, 1, ah1, bh1);
        #pragma unroll
        for (int mt = 0; mt < 4; mt++)
            #pragma unroll
            for (int nt = 0; nt < 4; nt++)
                mma_f16(acc[mt][nt], ah0[mt], bh0[nt]);
        __syncthreads();
        buf ^= 1;
    }
    // drain: last window's g1
    #pragma unroll
    for (int mt = 0; mt < 4; mt++)
        #pragma unroll
        for (int nt = 0; nt < 4; nt++)
            mma_f16(acc[mt][nt], ah1[mt], bh1[nt]);

    const int gid = l >> 2, qid = l & 3;
    #pragma unroll
    for (int mt = 0; mt < 4; mt++) {
        #pragma unroll
        for (int nt = 0; nt < 4; nt++) {
            int n0 = bn + wn * 32 + nt * 8 + qid * 2;
            float bx = bias[n0], by = bias[n0 + 1];
            #pragma unroll
            for (int half = 0; half < 2; half++) {
                int m = bm + wm * 64 + mt * 16 + gid + half * 8;
                float cx = acc[mt][nt][half*2 + 0] + bx;
                float cy = acc[mt][nt][half*2 + 1] + by;
                if (EPILOGUE == 0) {
                    int b = m >> 10, t = m & 1023;
                    int s = n0 >> 10, r = n0 & 1023;
                    int hh = r >> 6, d = r & 63;
                    size_t off = ((size_t)(b*NH + hh)*SEQ + t) * HD + d;
                    __half* dh = (s == 0 ? oq : (s == 1 ? ok : ov));
                    *(unsigned*)(dh + off) = pack_h2(cx, cy);
                } else {
                    float2 v2 = {cx, cy};
                    *(float2*)(outf + (size_t)m * N + n0) = v2;
                }
            }
        }
    }
}

// ---------------- fp16 tensor-core flash attention ----------------
// CTA: 128 q rows of one (b,h); key tiles of 64. 8 warps, warp = 16 rows.
#define QST 72
#define KST 72
#define VST 72
#define SM_Q 0
#define SM_K (128*QST)
#define SM_V (128*QST + 64*KST)
#define SM_TOT (128*QST + 64*KST + 64*VST)
#define ATTN_SMEM (SM_TOT*2 + 1024)

__global__ __launch_bounds__(256)
void flash_attn_f16(const __half* __restrict__ q16, const __half* __restrict__ k16,
                    const __half* __restrict__ v16,
                    const unsigned char* __restrict__ pad, const float* __restrict__ scale_p,
                    __half* __restrict__ outa)
{
    extern __shared__ __half smh[];
    unsigned char* spad = (unsigned char*)(smh + SM_TOT);
    const unsigned sbase = (unsigned)__cvta_generic_to_shared(smh);

    const int bh = blockIdx.x;
    const int b = bh >> 4, h = bh & 15;
    const int qb = (int)(gridDim.y - 1) - (int)blockIdx.y;   // heavy first
    const int q0 = qb * 128;
    const int tid = threadIdx.x;
    const int wid = tid >> 5, l = tid & 31;
    const int gid = l >> 2, qd = l & 3;
    const float scale = *scale_p;

    const int brow = ((l >> 4) & 1) * 8 + (l & 7);
    const int bcol = ((l >> 3) & 1) * 8;

    ((int*)spad)[tid] = ((const int*)(pad + (size_t)b*SEQ))[tid];

    // Q tile (persistent)
    {
        const __half* qs = q16 + ((size_t)bh*SEQ + q0)*HD;
        #pragma unroll
        for (int it = 0; it < 4; it++) {
            int lin = it*256 + tid;
            int row = lin >> 3, seg = lin & 7;
            cp16(sbase + (SM_Q + row*QST)*2 + seg*16, qs + (size_t)row*HD + seg*8);
        }
        asm volatile("cp.async.commit_group;\ncp.async.wait_group 0;\n" ::: "memory");
    }
    __syncthreads();

    unsigned qf[4][4];
    {
        int row = wid*16 + (l & 15);
        int csel = (l >> 4) * 8;
        #pragma unroll
        for (int ks = 0; ks < 4; ks++)
            ldsm4(qf[ks], sbase + (SM_Q + row*QST + ks*16 + csel)*2);
    }

    float O[8][4];
    #pragma unroll
    for (int nt = 0; nt < 8; nt++)
        #pragma unroll
        for (int r = 0; r < 4; r++) O[nt][r] = 0.f;
    float mrow[2] = {-1e30f, -1e30f};
    float lrow[2] = {0.f, 0.f};

    const int r0g = q0 + wid*16 + gid;
    const int r1g = r0g + 8;
    const int nkt = 2*qb + 2;

    for (int kt = 0; kt < nkt; kt++) {
        const int kb = kt * 64;
        __syncthreads();

        // K tile via cp.async
        {
            const __half* ks_ = k16 + ((size_t)bh*SEQ + kb)*HD;
            #pragma unroll
            for (int it = 0; it < 2; it++) {
                int lin = it*256 + tid;
                int row = lin >> 3, seg = lin & 7;
                cp16(sbase + (SM_K + row*KST)*2 + seg*16, ks_ + (size_t)row*HD + seg*8);
            }
            asm volatile("cp.async.commit_group;\n" ::: "memory");
        }
        // V tile, transposed [d][key]
        {
            int t = tid >> 2;
            int db = (tid & 3) * 16;
            const __half* vs = v16 + ((size_t)bh*SEQ + kb + t)*HD + db;
            #pragma unroll
            for (int j = 0; j < 4; j++) {
                uint2 u = *(const uint2*)(vs + j*4);
                __half2 a = *(__half2*)&u.x;
                __half2 c = *(__half2*)&u.y;
                smh[SM_V + (db + j*4 + 0)*VST + t] = a.x;
                smh[SM_V + (db + j*4 + 1)*VST + t] = a.y;
                smh[SM_V + (db + j*4 + 2)*VST + t] = c.x;
                smh[SM_V + (db + j*4 + 3)*VST + t] = c.y;
            }
        }
        asm volatile("cp.async.wait_group 0;\n" ::: "memory");
        __syncthreads();

        // ---- S = Q K^T ----
        float sacc[8][4];
        #pragma unroll
        for (int nt = 0; nt < 8; nt++)
            #pragma unroll
            for (int r = 0; r < 4; r++) sacc[nt][r] = 0.f;

        #pragma unroll
        for (int ks = 0; ks < 4; ks++) {
            #pragma unroll
            for (int p = 0; p < 4; p++) {
                unsigned k4[4];
                ldsm4(k4, sbase + (SM_K + (p*16 + brow)*KST + ks*16 + bcol)*2);
                unsigned b0[2] = {k4[0], k4[1]}, b1[2] = {k4[2], k4[3]};
                mma_f16(sacc[2*p],   qf[ks], b0);
                mma_f16(sacc[2*p+1], qf[ks], b1);
            }
        }

        // ---- scale + mask + online softmax ----
        float tmax0 = -1e30f, tmax1 = -1e30f;
        const bool do_causal = (kb + 63 > q0 + wid*16);
        #pragma unroll
        for (int nt = 0; nt < 8; nt++) {
            int c0 = kb + nt*8 + qd*2;
            bool pm0 = spad[c0] != 0, pm1 = spad[c0+1] != 0;
            float v00 = sacc[nt][0] * scale;
            float v01 = sacc[nt][1] * scale;
            float v10 = sacc[nt][2] * scale;
            float v11 = sacc[nt][3] * scale;
            if (pm0) { v00 = -1e30f; v10 = -1e30f; }
            if (pm1) { v01 = -1e30f; v11 = -1e30f; }
            if (do_causal) {
                if (c0   > r0g) v00 = -1e30f;
                if (c0+1 > r0g) v01 = -1e30f;
                if (c0   > r1g) v10 = -1e30f;
                if (c0+1 > r1g) v11 = -1e30f;
            }
            sacc[nt][0] = v00; sacc[nt][1] = v01;
            sacc[nt][2] = v10; sacc[nt][3] = v11;
            tmax0 = fmaxf(tmax0, fmaxf(v00, v01));
            tmax1 = fmaxf(tmax1, fmaxf(v10, v11));
        }
        tmax0 = fmaxf(tmax0, __shfl_xor_sync(0xffffffffu, tmax0, 1));
        tmax0 = fmaxf(tmax0, __shfl_xor_sync(0xffffffffu, tmax0, 2));
        tmax1 = fmaxf(tmax1, __shfl_xor_sync(0xffffffffu, tmax1, 1));
        tmax1 = fmaxf(tmax1, __shfl_xor_sync(0xffffffffu, tmax1, 2));

        float mn0 = fmaxf(mrow[0], tmax0);
        float mn1 = fmaxf(mrow[1], tmax1);
        float cf0 = __expf(mrow[0] - mn0);
        float cf1 = __expf(mrow[1] - mn1);
        mrow[0] = mn0; mrow[1] = mn1;

        float rs0 = 0.f, rs1 = 0.f;
        unsigned pf[8][2];
        #pragma unroll
        for (int nt = 0; nt < 8; nt++) {
            float p00 = __expf(sacc[nt][0] - mn0);
            float p01 = __expf(sacc[nt][1] - mn0);
            float p10 = __expf(sacc[nt][2] - mn1);
            float p11 = __expf(sacc[nt][3] - mn1);
            rs0 += p00 + p01;
            rs1 += p10 + p11;
            pf[nt][0] = pack_h2(p00, p01);
            pf[nt][1] = pack_h2(p10, p11);
        }
        rs0 += __shfl_xor_sync(0xffffffffu, rs0, 1);
        rs0 += __shfl_xor_sync(0xffffffffu, rs0, 2);
        rs1 += __shfl_xor_sync(0xffffffffu, rs1, 1);
        rs1 += __shfl_xor_sync(0xffffffffu, rs1, 2);
        lrow[0] = lrow[0] * cf0 + rs0;
        lrow[1] = lrow[1] * cf1 + rs1;
        #pragma unroll
        for (int nt = 0; nt < 8; nt++) {
            O[nt][0] *= cf0; O[nt][1] *= cf0;
            O[nt][2] *= cf1; O[nt][3] *= cf1;
        }

        // ---- O += P V ----
        #pragma unroll
        for (int ks = 0; ks < 4; ks++) {
            unsigned pa[4] = {pf[2*ks][0], pf[2*ks][1], pf[2*ks+1][0], pf[2*ks+1][1]};
            #pragma unroll
            for (int p = 0; p < 4; p++) {
                unsigned v4[4];
                ldsm4(v4, sbase + (SM_V + (p*16 + brow)*VST + ks*16 + bcol)*2);
                unsigned b0[2] = {v4[0], v4[1]}, b1[2] = {v4[2], v4[3]};
                mma_f16(O[2*p],   pa, b0);
                mma_f16(O[2*p+1], pa, b1);
            }
        }
    }

    // ---- epilogue: normalize, store fp16 [b, t, h*64+d] ----
    float inv0 = 1.f / lrow[0];
    float inv1 = 1.f / lrow[1];
    #pragma unroll
    for (int nt = 0; nt < 8; nt++) {
        float o00 = O[nt][0] * inv0, o01 = O[nt][1] * inv0;
        float o10 = O[nt][2] * inv1, o11 = O[nt][3] * inv1;
        int col = h*HD + nt*8 + qd*2;
        *(unsigned*)(outa + (size_t)(b*SEQ + r0g) * FEAT + col) = pack_h2(o00, o01);
        *(unsigned*)(outa + (size_t)(b*SEQ + r1g) * FEAT + col) = pack_h2(o10, o11);
    }
}

// ---------------- launch ----------------
extern "C" void kernel_launch(void* const* d_in, const int* in_sizes, int n_in,
                              void* d_out, int out_size)
{
    const float* x    = (const float*)d_in[0];
    const unsigned char* pad = (const unsigned char*)d_in[1];
    const float* Wqkv = (const float*)d_in[2];
    const float* bqkv = (const float*)d_in[3];
    const float* Wp   = (const float*)d_in[4];
    const float* bp   = (const float*)d_in[5];
    const float* scale = (const float*)d_in[6];
    float* out = (float*)d_out;

    __half *x16, *wq16, *wp16, *a16, *q16, *k16, *v16;
    cudaGetSymbolAddress((void**)&x16, g_x16);
    cudaGetSymbolAddress((void**)&wq16, g_wq16);
    cudaGetSymbolAddress((void**)&wp16, g_wp16);
    cudaGetSymbolAddress((void**)&a16, g_a16);
    cudaGetSymbolAddress((void**)&q16, g_q16);
    cudaGetSymbolAddress((void**)&k16, g_k16);
    cudaGetSymbolAddress((void**)&v16, g_v16);

    cudaFuncSetAttribute(gemm_f16<0>, cudaFuncAttributeMaxDynamicSharedMemorySize, GEMM_SMEM);
    cudaFuncSetAttribute(gemm_f16<1>, cudaFuncAttributeMaxDynamicSharedMemorySize, GEMM_SMEM);
    cudaFuncSetAttribute(flash_attn_f16, cudaFuncAttributeMaxDynamicSharedMemorySize, ATTN_SMEM);

    int n4tot = N4_X + N4_WQ + N4_WP;
    cvt3_fp16<<<(n4tot + 255)/256, 256>>>(x, Wqkv, Wp, x16, wq16, wp16);

    dim3 g1(3072/128, 8192/128);
    gemm_f16<0><<<g1, 256, GEMM_SMEM>>>(x16, wq16, bqkv, nullptr, q16, k16, v16, 3072, 1024);

    dim3 g2(BATCH*NH, SEQ/128);
    flash_attn_f16<<<g2, 256, ATTN_SMEM>>>(q16, k16, v16, pad, scale, a16);

    dim3 g3(1024/128, 8192/128);
    gemm_f16<1><<<g3, 256, GEMM_SMEM>>>(a16, wp16, bp, out, nullptr, nullptr, nullptr, 1024, 1024);
}

// round 15
// speedup vs baseline: 1.2820x; 1.0091x over previous
#include <cuda_runtime.h>
#include <cuda_fp16.h>

#define FEAT 1024
#define NH   16
#define HD   64
#define BATCH 8
#define SEQ  1024

// ---------------- scratch (device globals; no allocation) ----------------
__device__ __half g_x16[8192*1024];
__device__ __half g_wq16[3072*1024];
__device__ __half g_wp16[1024*1024];
__device__ __half g_a16[8192*1024];
__device__ __half g_q16[8192*1024];
__device__ __half g_k16[8192*1024];
__device__ __half g_v16[8192*1024];

// ---------------- helpers ----------------
__device__ __forceinline__ void ldsm4(unsigned r[4], unsigned addr) {
    asm volatile("ldmatrix.sync.aligned.m8n8.x4.shared.b16 {%0,%1,%2,%3}, [%4];\n"
                 : "=r"(r[0]), "=r"(r[1]), "=r"(r[2]), "=r"(r[3]) : "r"(addr));
}
__device__ __forceinline__ void mma_f16(float c[4], const unsigned a[4], const unsigned b[2]) {
    asm volatile("mma.sync.aligned.m16n8k16.row.col.f32.f16.f16.f32 "
                 "{%0,%1,%2,%3}, {%4,%5,%6,%7}, {%8,%9}, {%0,%1,%2,%3};\n"
                 : "+f"(c[0]), "+f"(c[1]), "+f"(c[2]), "+f"(c[3])
                 : "r"(a[0]), "r"(a[1]), "r"(a[2]), "r"(a[3]), "r"(b[0]), "r"(b[1]));
}
__device__ __forceinline__ void cp16(unsigned dst, const void* src) {
    asm volatile("cp.async.cg.shared.global [%0], [%1], 16;\n" :: "r"(dst), "l"(src));
}
__device__ __forceinline__ unsigned pack_h2(float lo, float hi) {
    __half2 h = __floats2half2_rn(lo, hi);
    return *(unsigned*)&h;
}

// ---------------- fp32 -> fp16 convert (all three tensors, one launch) ----------------
#define N4_X  (8192*1024/4)
#define N4_WQ (3072*1024/4)
#define N4_WP (1024*1024/4)
__global__ __launch_bounds__(256)
void cvt3_fp16(const float* __restrict__ x, const float* __restrict__ wq,
               const float* __restrict__ wp,
               __half* __restrict__ x16, __half* __restrict__ wq16,
               __half* __restrict__ wp16)
{
    int i = blockIdx.x * blockDim.x + threadIdx.x;
    const float* s; __half* d; int j;
    if (i < N4_X)                 { s = x;  d = x16;  j = i; }
    else if (i < N4_X + N4_WQ)    { s = wq; d = wq16; j = i - N4_X; }
    else if (i < N4_X + N4_WQ + N4_WP) { s = wp; d = wp16; j = i - N4_X - N4_WQ; }
    else return;
    float4 v = ((const float4*)s)[j];
    uint2 o;
    o.x = pack_h2(v.x, v.y);
    o.y = pack_h2(v.z, v.w);
    ((uint2*)d)[j] = o;
}

// ---------------- fp16 tensor-core GEMM: C = A @ W^T + bias ----------------
// 256 threads / 8 warps, warp tile 64x32, K-chunk 32, double-buffered smem.
// ONE __syncthreads per window: wait_group -> sync -> issue-into-old-buffer.
// Cross-window fragment holding: g1 fragments MMA'd after the next window's sync.
#define AST 40                   // fp16 elems per smem row (32 + 8 pad)
#define PLANE_B (128*AST*2)      // 10240 bytes per plane
#define BUF_B (2*PLANE_B)        // A, W = 20480
#define GEMM_SMEM (2*BUF_B)      // 40960 double-buffered

// EPILOGUE 0: scatter fp16 to q/k/v ; EPILOGUE 1: fp32 row-major to outf
template<int EPILOGUE>
__global__ __launch_bounds__(256, 2)
void gemm_f16(const __half* __restrict__ A16, const __half* __restrict__ W16,
              const float* __restrict__ bias, float* __restrict__ outf,
              __half* __restrict__ oq, __half* __restrict__ ok, __half* __restrict__ ov,
              int N, int K)
{
    extern __shared__ __half sm[];
    const int tid = threadIdx.x;
    const int bm = blockIdx.y * 128, bn = blockIdx.x * 128;
    const int w = tid >> 5, l = tid & 31;
    const int wm = w >> 2, wn = w & 3;       // 2x4 warp grid; warp tile 64x32

    const int lrow = tid >> 1;
    const int lcol = (tid & 1) * 16;
    const __half* gA = A16 + (size_t)(bm + lrow) * K + lcol;
    const __half* gB = W16 + (size_t)(bn + lrow) * K + lcol;

    const unsigned sbase = (unsigned)__cvta_generic_to_shared(sm);
    const unsigned sst = sbase + lrow * (AST*2) + lcol * 2;

    float acc[4][4][4];
    #pragma unroll
    for (int i = 0; i < 4; i++)
        #pragma unroll
        for (int j = 0; j < 4; j++)
            #pragma unroll
            for (int r = 0; r < 4; r++) acc[i][j][r] = 0.f;

    auto issue = [&](int k0, int buf) {
        unsigned d = sst + buf * BUF_B;
        cp16(d,             gA + k0); cp16(d + 16,             gA + k0 + 8);
        cp16(d + PLANE_B,   gB + k0); cp16(d + PLANE_B + 16,   gB + k0 + 8);
        asm volatile("cp.async.commit_group;\n" ::: "memory");
    };

    auto ldsm_frags = [&](unsigned base, int g, unsigned ah[4][4], unsigned bh[4][2]) {
        const int acol = g * 16 + (l >> 4) * 8;
        #pragma unroll
        for (int mt = 0; mt < 4; mt++) {
            int row = wm * 64 + mt * 16 + (l & 15);
            ldsm4(ah[mt], base + row * (AST*2) + acol * 2);
        }
        const int quad = l >> 3;
        const int nsub = quad >> 1, khalf = quad & 1;
        #pragma unroll
        for (int p = 0; p < 2; p++) {
            int row = wn * 32 + (p*2 + nsub) * 8 + (l & 7);
            int col = g * 16 + khalf * 8;
            unsigned t[4];
            ldsm4(t, base + PLANE_B + row * (AST*2) + col * 2);
            bh[p*2][0] = t[0]; bh[p*2][1] = t[1];
            bh[p*2+1][0] = t[2]; bh[p*2+1][1] = t[3];
        }
    };

    unsigned ah0[4][4], bh0[4][2];     // g0 fragments (current window)
    unsigned ah1[4][4], bh1[4][2];     // g1 fragments (held across boundary)

    issue(0, 0);
    int buf = 0;
    for (int k0 = 0; k0 < K; k0 += 32) {
        asm volatile("cp.async.wait_group 0;\n" ::: "memory");
        __syncthreads();     // data visible to all; all prior reads of old buf done
        if (k0 + 32 < K) issue(k0 + 32, buf ^ 1);

        unsigned base = sbase + buf * BUF_B;
        ldsm_frags(base, 0, ah0, bh0);
        if (k0 > 0) {
            #pragma unroll
            for (int mt = 0; mt < 4; mt++)
                #pragma unroll
                for (int nt = 0; nt < 4; nt++)
                    mma_f16(acc[mt][nt], ah1[mt], bh1[nt]);
        }
        ldsm_frags(base, 1, ah1, bh1);
        #pragma unroll
        for (int mt = 0; mt < 4; mt++)
            #pragma unroll
            for (int nt = 0; nt < 4; nt++)
                mma_f16(acc[mt][nt], ah0[mt], bh0[nt]);
        buf ^= 1;
    }
    // drain: last window's g1
    #pragma unroll
    for (int mt = 0; mt < 4; mt++)
        #pragma unroll
        for (int nt = 0; nt < 4; nt++)
            mma_f16(acc[mt][nt], ah1[mt], bh1[nt]);

    const int gid = l >> 2, qid = l & 3;
    #pragma unroll
    for (int mt = 0; mt < 4; mt++) {
        #pragma unroll
        for (int nt = 0; nt < 4; nt++) {
            int n0 = bn + wn * 32 + nt * 8 + qid * 2;
            float bx = bias[n0], by = bias[n0 + 1];
            #pragma unroll
            for (int half = 0; half < 2; half++) {
                int m = bm + wm * 64 + mt * 16 + gid + half * 8;
                float cx = acc[mt][nt][half*2 + 0] + bx;
                float cy = acc[mt][nt][half*2 + 1] + by;
                if (EPILOGUE == 0) {
                    int b = m >> 10, t = m & 1023;
                    int s = n0 >> 10, r = n0 & 1023;
                    int hh = r >> 6, d = r & 63;
                    size_t off = ((size_t)(b*NH + hh)*SEQ + t) * HD + d;
                    __half* dh = (s == 0 ? oq : (s == 1 ? ok : ov));
                    *(unsigned*)(dh + off) = pack_h2(cx, cy);
                } else {
                    float2 v2 = {cx, cy};
                    *(float2*)(outf + (size_t)m * N + n0) = v2;
                }
            }
        }
    }
}

// ---------------- fp16 tensor-core flash attention ----------------
// CTA: 128 q rows of one (b,h); key tiles of 64. 8 warps, warp = 16 rows.
// Double-buffered K (cp.async) and V (LDG early + STS late). ONE barrier per tile.
#define QST 72
#define KST 72
#define VST 72
#define SM_Q  0
#define SM_K0 (128*QST)
#define SM_K1 (SM_K0 + 64*KST)
#define SM_V0 (SM_K1 + 64*KST)
#define SM_V1 (SM_V0 + 64*VST)
#define SM_TOT (SM_V1 + 64*VST)
#define ATTN_SMEM (SM_TOT*2 + 1024)

__global__ __launch_bounds__(256)
void flash_attn_f16(const __half* __restrict__ q16, const __half* __restrict__ k16,
                    const __half* __restrict__ v16,
                    const unsigned char* __restrict__ pad, const float* __restrict__ scale_p,
                    __half* __restrict__ outa)
{
    extern __shared__ __half smh[];
    unsigned char* spad = (unsigned char*)(smh + SM_TOT);
    const unsigned sbase = (unsigned)__cvta_generic_to_shared(smh);

    const int bh = blockIdx.x;
    const int b = bh >> 4, h = bh & 15;
    const int qb = (int)(gridDim.y - 1) - (int)blockIdx.y;   // heavy first
    const int q0 = qb * 128;
    const int tid = threadIdx.x;
    const int wid = tid >> 5, l = tid & 31;
    const int gid = l >> 2, qd = l & 3;
    const float scale = *scale_p;

    const int brow = ((l >> 4) & 1) * 8 + (l & 7);
    const int bcol = ((l >> 3) & 1) * 8;

    const int vrow = tid >> 2;             // V stage: row 0..63
    const int vdb  = (tid & 3) * 16;       // V stage: d-base

    const int SM_K[2] = {SM_K0, SM_K1};
    const int SM_V[2] = {SM_V0, SM_V1};

    ((int*)spad)[tid] = ((const int*)(pad + (size_t)b*SEQ))[tid];

    const int nkt = 2*qb + 2;

    // ---- prologue: Q + K0 via cp.async (one group); V0 via LDG ----
    {
        const __half* qs = q16 + ((size_t)bh*SEQ + q0)*HD;
        #pragma unroll
        for (int it = 0; it < 4; it++) {
            int lin = it*256 + tid;
            int row = lin >> 3, seg = lin & 7;
            cp16(sbase + (SM_Q + row*QST)*2 + seg*16, qs + (size_t)row*HD + seg*8);
        }
        const __half* ks_ = k16 + (size_t)bh*SEQ*HD;
        #pragma unroll
        for (int it = 0; it < 2; it++) {
            int lin = it*256 + tid;
            int row = lin >> 3, seg = lin & 7;
            cp16(sbase + (SM_K0 + row*KST)*2 + seg*16, ks_ + (size_t)row*HD + seg*8);
        }
        asm volatile("cp.async.commit_group;\n" ::: "memory");
    }
    uint2 vreg[4];
    {
        const __half* vs = v16 + ((size_t)bh*SEQ + vrow)*HD + vdb;
        #pragma unroll
        for (int j = 0; j < 4; j++) vreg[j] = *(const uint2*)(vs + j*4);
    }
    asm volatile("cp.async.wait_group 0;\n" ::: "memory");
    __syncthreads();
    // STS V0; preload Q fragments
    #pragma unroll
    for (int j = 0; j < 4; j++) {
        __half2 a = *(__half2*)&vreg[j].x;
        __half2 c = *(__half2*)&vreg[j].y;
        smh[SM_V0 + (vdb + j*4 + 0)*VST + vrow] = a.x;
        smh[SM_V0 + (vdb + j*4 + 1)*VST + vrow] = a.y;
        smh[SM_V0 + (vdb + j*4 + 2)*VST + vrow] = c.x;
        smh[SM_V0 + (vdb + j*4 + 3)*VST + vrow] = c.y;
    }
    unsigned qf[4][4];
    {
        int row = wid*16 + (l & 15);
        int csel = (l >> 4) * 8;
        #pragma unroll
        for (int ks = 0; ks < 4; ks++)
            ldsm4(qf[ks], sbase + (SM_Q + row*QST + ks*16 + csel)*2);
    }
    __syncthreads();   // V0 visible to all

    float O[8][4];
    #pragma unroll
    for (int nt = 0; nt < 8; nt++)
        #pragma unroll
        for (int r = 0; r < 4; r++) O[nt][r] = 0.f;
    float mrow[2] = {-1e30f, -1e30f};
    float lrow[2] = {0.f, 0.f};

    const int r0g = q0 + wid*16 + gid;
    const int r1g = r0g + 8;

    for (int kt = 0; kt < nkt; kt++) {
        const int kb = kt * 64;
        const int c = kt & 1, n = c ^ 1;
        const bool more = (kt + 1) < nkt;

        if (kt > 0) {
            asm volatile("cp.async.wait_group 0;\n" ::: "memory");
            __syncthreads();   // K(kt) + V(kt) visible; old-buffer reads done
        }
        if (more) {
            // cp.async K(kt+1) into buffer n
            const __half* ks_ = k16 + ((size_t)bh*SEQ + kb + 64)*HD;
            #pragma unroll
            for (int it = 0; it < 2; it++) {
                int lin = it*256 + tid;
                int row = lin >> 3, seg = lin & 7;
                cp16(sbase + (SM_K[n] + row*KST)*2 + seg*16, ks_ + (size_t)row*HD + seg*8);
            }
            asm volatile("cp.async.commit_group;\n" ::: "memory");
            // LDG V(kt+1) -> regs (overlaps QK^T + softmax)
            const __half* vs = v16 + ((size_t)bh*SEQ + kb + 64 + vrow)*HD + vdb;
            #pragma unroll
            for (int j = 0; j < 4; j++) vreg[j] = *(const uint2*)(vs + j*4);
        }

        // ---- S = Q K^T (from K buffer c) ----
        float sacc[8][4];
        #pragma unroll
        for (int nt = 0; nt < 8; nt++)
            #pragma unroll
            for (int r = 0; r < 4; r++) sacc[nt][r] = 0.f;

        #pragma unroll
        for (int ks = 0; ks < 4; ks++) {
            #pragma unroll
            for (int p = 0; p < 4; p++) {
                unsigned k4[4];
                ldsm4(k4, sbase + (SM_K[c] + (p*16 + brow)*KST + ks*16 + bcol)*2);
                unsigned b0[2] = {k4[0], k4[1]}, b1[2] = {k4[2], k4[3]};
                mma_f16(sacc[2*p],   qf[ks], b0);
                mma_f16(sacc[2*p+1], qf[ks], b1);
            }
        }

        // ---- scale + mask + online softmax ----
        float tmax0 = -1e30f, tmax1 = -1e30f;
        const bool do_causal = (kb + 63 > q0 + wid*16);
        #pragma unroll
        for (int nt = 0; nt < 8; nt++) {
            int c0 = kb + nt*8 + qd*2;
            bool pm0 = spad[c0] != 0, pm1 = spad[c0+1] != 0;
            float v00 = sacc[nt][0] * scale;
            float v01 = sacc[nt][1] * scale;
            float v10 = sacc[nt][2] * scale;
            float v11 = sacc[nt][3] * scale;
            if (pm0) { v00 = -1e30f; v10 = -1e30f; }
            if (pm1) { v01 = -1e30f; v11 = -1e30f; }
            if (do_causal) {
                if (c0   > r0g) v00 = -1e30f;
                if (c0+1 > r0g) v01 = -1e30f;
                if (c0   > r1g) v10 = -1e30f;
                if (c0+1 > r1g) v11 = -1e30f;
            }
            sacc[nt][0] = v00; sacc[nt][1] = v01;
            sacc[nt][2] = v10; sacc[nt][3] = v11;
            tmax0 = fmaxf(tmax0, fmaxf(v00, v01));
            tmax1 = fmaxf(tmax1, fmaxf(v10, v11));
        }
        tmax0 = fmaxf(tmax0, __shfl_xor_sync(0xffffffffu, tmax0, 1));
        tmax0 = fmaxf(tmax0, __shfl_xor_sync(0xffffffffu, tmax0, 2));
        tmax1 = fmaxf(tmax1, __shfl_xor_sync(0xffffffffu, tmax1, 1));
        tmax1 = fmaxf(tmax1, __shfl_xor_sync(0xffffffffu, tmax1, 2));

        float mn0 = fmaxf(mrow[0], tmax0);
        float mn1 = fmaxf(mrow[1], tmax1);
        float cf0 = __expf(mrow[0] - mn0);
        float cf1 = __expf(mrow[1] - mn1);
        mrow[0] = mn0; mrow[1] = mn1;

        float rs0 = 0.f, rs1 = 0.f;
        unsigned pf[8][2];
        #pragma unroll
        for (int nt = 0; nt < 8; nt++) {
            float p00 = __expf(sacc[nt][0] - mn0);
            float p01 = __expf(sacc[nt][1] - mn0);
            float p10 = __expf(sacc[nt][2] - mn1);
            float p11 = __expf(sacc[nt][3] - mn1);
            rs0 += p00 + p01;
            rs1 += p10 + p11;
            pf[nt][0] = pack_h2(p00, p01);
            pf[nt][1] = pack_h2(p10, p11);
        }
        rs0 += __shfl_xor_sync(0xffffffffu, rs0, 1);
        rs0 += __shfl_xor_sync(0xffffffffu, rs0, 2);
        rs1 += __shfl_xor_sync(0xffffffffu, rs1, 1);
        rs1 += __shfl_xor_sync(0xffffffffu, rs1, 2);
        lrow[0] = lrow[0] * cf0 + rs0;
        lrow[1] = lrow[1] * cf1 + rs1;
        #pragma unroll
        for (int nt = 0; nt < 8; nt++) {
            O[nt][0] *= cf0; O[nt][1] *= cf0;
            O[nt][2] *= cf1; O[nt][3] *= cf1;
        }

        // ---- STS V(kt+1) into buffer n (published by next top barrier) ----
        if (more) {
            #pragma unroll
            for (int j = 0; j < 4; j++) {
                __half2 a = *(__half2*)&vreg[j].x;
                __half2 cc = *(__half2*)&vreg[j].y;
                smh[SM_V[n] + (vdb + j*4 + 0)*VST + vrow] = a.x;
                smh[SM_V[n] + (vdb + j*4 + 1)*VST + vrow] = a.y;
                smh[SM_V[n] + (vdb + j*4 + 2)*VST + vrow] = cc.x;
                smh[SM_V[n] + (vdb + j*4 + 3)*VST + vrow] = cc.y;
            }
        }

        // ---- O += P V (from V buffer c) ----
        #pragma unroll
        for (int ks = 0; ks < 4; ks++) {
            unsigned pa[4] = {pf[2*ks][0], pf[2*ks][1], pf[2*ks+1][0], pf[2*ks+1][1]};
            #pragma unroll
            for (int p = 0; p < 4; p++) {
                unsigned v4[4];
                ldsm4(v4, sbase + (SM_V[c] + (p*16 + brow)*VST + ks*16 + bcol)*2);
                unsigned b0[2] = {v4[0], v4[1]}, b1[2] = {v4[2], v4[3]};
                mma_f16(O[2*p],   pa, b0);
                mma_f16(O[2*p+1], pa, b1);
            }
        }
    }

    // ---- epilogue: normalize, store fp16 [b, t, h*64+d] ----
    float inv0 = 1.f / lrow[0];
    float inv1 = 1.f / lrow[1];
    #pragma unroll
    for (int nt = 0; nt < 8; nt++) {
        float o00 = O[nt][0] * inv0, o01 = O[nt][1] * inv0;
        float o10 = O[nt][2] * inv1, o11 = O[nt][3] * inv1;
        int col = h*HD + nt*8 + qd*2;
        *(unsigned*)(outa + (size_t)(b*SEQ + r0g) * FEAT + col) = pack_h2(o00, o01);
        *(unsigned*)(outa + (size_t)(b*SEQ + r1g) * FEAT + col) = pack_h2(o10, o11);
    }
}

// ---------------- launch ----------------
extern "C" void kernel_launch(void* const* d_in, const int* in_sizes, int n_in,
                              void* d_out, int out_size)
{
    const float* x    = (const float*)d_in[0];
    const unsigned char* pad = (const unsigned char*)d_in[1];
    const float* Wqkv = (const float*)d_in[2];
    const float* bqkv = (const float*)d_in[3];
    const float* Wp   = (const float*)d_in[4];
    const float* bp   = (const float*)d_in[5];
    const float* scale = (const float*)d_in[6];
    float* out = (float*)d_out;

    __half *x16, *wq16, *wp16, *a16, *q16, *k16, *v16;
    cudaGetSymbolAddress((void**)&x16, g_x16);
    cudaGetSymbolAddress((void**)&wq16, g_wq16);
    cudaGetSymbolAddress((void**)&wp16, g_wp16);
    cudaGetSymbolAddress((void**)&a16, g_a16);
    cudaGetSymbolAddress((void**)&q16, g_q16);
    cudaGetSymbolAddress((void**)&k16, g_k16);
    cudaGetSymbolAddress((void**)&v16, g_v16);

    cudaFuncSetAttribute(gemm_f16<0>, cudaFuncAttributeMaxDynamicSharedMemorySize, GEMM_SMEM);
    cudaFuncSetAttribute(gemm_f16<1>, cudaFuncAttributeMaxDynamicSharedMemorySize, GEMM_SMEM);
    cudaFuncSetAttribute(flash_attn_f16, cudaFuncAttributeMaxDynamicSharedMemorySize, ATTN_SMEM);

    int n4tot = N4_X + N4_WQ + N4_WP;
    cvt3_fp16<<<(n4tot + 255)/256, 256>>>(x, Wqkv, Wp, x16, wq16, wp16);

    dim3 g1(3072/128, 8192/128);
    gemm_f16<0><<<g1, 256, GEMM_SMEM>>>(x16, wq16, bqkv, nullptr, q16, k16, v16, 3072, 1024);

    dim3 g2(BATCH*NH, SEQ/128);
    flash_attn_f16<<<g2, 256, ATTN_SMEM>>>(q16, k16, v16, pad, scale, a16);

    dim3 g3(1024/128, 8192/128);
    gemm_f16<1><<<g3, 256, GEMM_SMEM>>>(a16, wp16, bp, out, nullptr, nullptr, nullptr, 1024, 1024);
}